// round 8
// baseline (speedup 1.0000x reference)
#include <cuda_runtime.h>
#include <stdint.h>

// labels[b,l,i] = argmin_j ( tn[b,l,i] - cbn[i,j] )
//              = argmax_j cbn[i,j]            (tn constant over argmin axis j)
//              = argmax_j codebook[i,j]       (cbn = positive-scale affine of codebook)
// => output (float32) = per-row argmax of the 64x64 codebook, tiled B*L = 16384x.
//
// R7 post-mortem: 512 blocks regressed (4x redundant argmax, nothing to hide);
// grid sweep says 128 blocks is best and the kernel floor is ~4.6us. R8: the
// winning combination — 128 blocks (R6) + single-sync direct LDS.128 pattern
// read (R7), PER_THR=8.

static constexpr int QDIM    = 64;
static constexpr int TOTAL4  = (8 * 2048 * 64) / 4;   // 262144 float4 (4 MB)
static constexpr int NBLK    = 128;
static constexpr int PER_THR = TOTAL4 / (NBLK * 256); // 8 float4 per thread

// Monotone key: order-preserving f32 bits in [63:6], (63-j) in [5:0].
// u64-max => max value; among equal values, larger (63-j) => SMALLER j,
// i.e. first-index tie-break, matching jnp.argmin on (s - c_j).
__device__ __forceinline__ unsigned long long mono_key(float v, int j) {
    uint32_t u = __float_as_uint(v);
    u ^= (uint32_t)((int32_t)u >> 31) | 0x80000000u;   // ordered-uint transform
    return ((unsigned long long)u << 6) | (unsigned long long)(63 - j);
}

__device__ __forceinline__ unsigned long long kmax(unsigned long long a,
                                                   unsigned long long b) {
    return a > b ? a : b;
}

__global__ __launch_bounds__(256) void bestrq_fused4_kernel(
    const float4* __restrict__ cb4,       // codebook (64,64) as 1024 float4
    float4* __restrict__ out4)            // 262144 float4
{
    __shared__ alignas(16) float s_lbl[QDIM];   // float labels, float4-readable

    const int t    = threadIdx.x;
    const int row  = t >> 2;              // 0..63  (4 threads per row)
    const int part = t & 3;               // 0..3   (16 elements each)

    // ---- Load this thread's 16 row elements (4 independent LDG.128) ----
    const float4* p = cb4 + row * 16 + part * 4;
    float4 a = p[0], b = p[1], c = p[2], d = p[3];

    // ---- In-register argmax over 16 elements via monotone keys ----
    const int bj = part * 16;
    unsigned long long k;
    k =      kmax(kmax(mono_key(a.x, bj + 0), mono_key(a.y, bj + 1)),
                  kmax(mono_key(a.z, bj + 2), mono_key(a.w, bj + 3)));
    k = kmax(k, kmax(kmax(mono_key(b.x, bj + 4), mono_key(b.y, bj + 5)),
                     kmax(mono_key(b.z, bj + 6), mono_key(b.w, bj + 7))));
    k = kmax(k, kmax(kmax(mono_key(c.x, bj + 8), mono_key(c.y, bj + 9)),
                     kmax(mono_key(c.z, bj + 10), mono_key(c.w, bj + 11))));
    k = kmax(k, kmax(kmax(mono_key(d.x, bj + 12), mono_key(d.y, bj + 13)),
                     kmax(mono_key(d.z, bj + 14), mono_key(d.w, bj + 15))));

    // ---- Reduce across the 4 lanes of this row ----
    k = kmax(k, __shfl_xor_sync(0xFFFFFFFFu, k, 1));
    k = kmax(k, __shfl_xor_sync(0xFFFFFFFFu, k, 2));

    if (part == 0) s_lbl[row] = (float)(63 - (int)(k & 63));
    __syncthreads();                      // the ONLY block sync

    // ---- Read this thread's pattern slot directly (aligned LDS.128) ----
    // Slot (t & 15) = rows 4*(t&15)..+3. All store offsets below are multiples
    // of 16 float4 (one 64-label period), so the slot depends only on t.
    const float4 v = *reinterpret_cast<const float4*>(&s_lbl[4 * (t & 15)]);

    const int base = blockIdx.x * (256 * PER_THR) + t;
#pragma unroll
    for (int kk = 0; kk < PER_THR; ++kk) {
        out4[base + kk * 256] = v;
    }
}

extern "C" void kernel_launch(void* const* d_in, const int* in_sizes, int n_in,
                              void* d_out, int out_size)
{
    (void)out_size;

    // Codebook selection by size (elements: 4096; bytes fallback: 16384).
    const float* codebook = nullptr;
    int max_sz = 0;
    for (int i = 0; i < n_in; ++i) if (in_sizes[i] > max_sz) max_sz = in_sizes[i];
    for (int i = 0; i < n_in; ++i) {
        if (in_sizes[i] == QDIM * QDIM) codebook = (const float*)d_in[i];
    }
    if (!codebook && max_sz > 8 * 1024 * 1024) {
        for (int i = 0; i < n_in; ++i) {
            if (in_sizes[i] == QDIM * QDIM * 4) codebook = (const float*)d_in[i];
        }
    }
    if (!codebook) codebook = (const float*)d_in[n_in - 1];

    bestrq_fused4_kernel<<<NBLK, 256>>>((const float4*)codebook, (float4*)d_out);
}

// round 9
// speedup vs baseline: 1.1198x; 1.1198x over previous
#include <cuda_runtime.h>
#include <stdint.h>

// labels[b,l,i] = argmin_j ( tn[b,l,i] - cbn[i,j] )
//              = argmax_j cbn[i,j]            (tn constant over argmin axis j)
//              = argmax_j codebook[i,j]       (cbn = positive-scale affine of codebook)
// => output (float32) = per-row argmax of the 64x64 codebook, tiled B*L = 16384x.
//
// R8 post-mortem: ncu body durs (5.25 / 5.70 / 5.09) moved OPPOSITE to bench
// durs (6.18 / 6.46 / 6.88) -> bench jitter ~±0.5us dominates; R8's body is the
// fastest measured. Keep it; micro-trim the post-barrier tail (unpredicated
// same-value STS, base hoisted above the sync) and re-bench.

static constexpr int QDIM    = 64;
static constexpr int TOTAL4  = (8 * 2048 * 64) / 4;   // 262144 float4 (4 MB)
static constexpr int NBLK    = 128;
static constexpr int PER_THR = TOTAL4 / (NBLK * 256); // 8 float4 per thread

// Monotone key: order-preserving f32 bits in [63:6], (63-j) in [5:0].
// u64-max => max value; among equal values, larger (63-j) => SMALLER j,
// i.e. first-index tie-break, matching jnp.argmin on (s - c_j).
__device__ __forceinline__ unsigned long long mono_key(float v, int j) {
    uint32_t u = __float_as_uint(v);
    u ^= (uint32_t)((int32_t)u >> 31) | 0x80000000u;   // ordered-uint transform
    return ((unsigned long long)u << 6) | (unsigned long long)(63 - j);
}

__device__ __forceinline__ unsigned long long kmax(unsigned long long a,
                                                   unsigned long long b) {
    return a > b ? a : b;
}

__global__ __launch_bounds__(256) void bestrq_fused5_kernel(
    const float4* __restrict__ cb4,       // codebook (64,64) as 1024 float4
    float4* __restrict__ out4)            // 262144 float4
{
    __shared__ alignas(16) float s_lbl[QDIM];   // float labels, float4-readable

    const int t    = threadIdx.x;
    const int row  = t >> 2;              // 0..63  (4 threads per row)
    const int part = t & 3;               // 0..3   (16 elements each)

    // ---- Load this thread's 16 row elements (4 independent LDG.128) ----
    const float4* p = cb4 + row * 16 + part * 4;
    float4 a = p[0], b = p[1], c = p[2], d = p[3];

    // Hoist the store base: post-barrier tail = LDS.128 + 8 STG only.
    const int base = blockIdx.x * (256 * PER_THR) + t;

    // ---- In-register argmax over 16 elements via monotone keys ----
    const int bj = part * 16;
    unsigned long long k;
    k =      kmax(kmax(mono_key(a.x, bj + 0), mono_key(a.y, bj + 1)),
                  kmax(mono_key(a.z, bj + 2), mono_key(a.w, bj + 3)));
    k = kmax(k, kmax(kmax(mono_key(b.x, bj + 4), mono_key(b.y, bj + 5)),
                     kmax(mono_key(b.z, bj + 6), mono_key(b.w, bj + 7))));
    k = kmax(k, kmax(kmax(mono_key(c.x, bj + 8), mono_key(c.y, bj + 9)),
                     kmax(mono_key(c.z, bj + 10), mono_key(c.w, bj + 11))));
    k = kmax(k, kmax(kmax(mono_key(d.x, bj + 12), mono_key(d.y, bj + 13)),
                     kmax(mono_key(d.z, bj + 14), mono_key(d.w, bj + 15))));

    // ---- Reduce across the 4 lanes of this row ----
    k = kmax(k, __shfl_xor_sync(0xFFFFFFFFu, k, 1));
    k = kmax(k, __shfl_xor_sync(0xFFFFFFFFu, k, 2));

    // All 4 lanes hold the identical reduced key: unpredicated same-value STS
    // to the same address (one lane wins; no divergent branch before the bar).
    s_lbl[row] = (float)(63 - (int)(k & 63));
    __syncthreads();                      // the ONLY block sync

    // ---- Read this thread's pattern slot directly (aligned LDS.128) ----
    // Slot (t & 15) = rows 4*(t&15)..+3. All store offsets below are multiples
    // of 16 float4 (one 64-label period), so the slot depends only on t.
    const float4 v = *reinterpret_cast<const float4*>(&s_lbl[4 * (t & 15)]);

#pragma unroll
    for (int kk = 0; kk < PER_THR; ++kk) {
        out4[base + kk * 256] = v;
    }
}

extern "C" void kernel_launch(void* const* d_in, const int* in_sizes, int n_in,
                              void* d_out, int out_size)
{
    (void)out_size;

    // Codebook selection by size (elements: 4096; bytes fallback: 16384).
    const float* codebook = nullptr;
    int max_sz = 0;
    for (int i = 0; i < n_in; ++i) if (in_sizes[i] > max_sz) max_sz = in_sizes[i];
    for (int i = 0; i < n_in; ++i) {
        if (in_sizes[i] == QDIM * QDIM) codebook = (const float*)d_in[i];
    }
    if (!codebook && max_sz > 8 * 1024 * 1024) {
        for (int i = 0; i < n_in; ++i) {
            if (in_sizes[i] == QDIM * QDIM * 4) codebook = (const float*)d_in[i];
        }
    }
    if (!codebook) codebook = (const float*)d_in[n_in - 1];

    bestrq_fused5_kernel<<<NBLK, 256>>>((const float4*)codebook, (float4*)d_out);
}